// round 7
// baseline (speedup 1.0000x reference)
#include <cuda_runtime.h>
#include <cuda_bf16.h>

#define NN 50000
#define KK 17
#define DIN 128
#define DOUT 64

// Scratch for projected features xp = x @ W : [N, 64] fp32 = 12.8 MB (fits in L2)
__device__ float g_xp[(size_t)NN * DOUT];

// ---------------------------------------------------------------------------
// Kernel 1: xp = x @ W (fp32). R4 version — at the FFMA floor (~22us).
// ---------------------------------------------------------------------------
__global__ void __launch_bounds__(256) gemm_kernel(
    const float* __restrict__ x, const float* __restrict__ wm)
{
    __shared__ float xs[128][32];
    __shared__ float ws[32][64];

    const int tid  = threadIdx.x;
    const int row0 = blockIdx.x * 128;
    const int c0   = (tid & 15) * 4;
    const int r0   = (tid >> 4) * 8;

    float acc[8][4];
#pragma unroll
    for (int i = 0; i < 8; i++)
#pragma unroll
        for (int j = 0; j < 4; j++) acc[i][j] = 0.f;

    for (int k0 = 0; k0 < DIN; k0 += 32) {
#pragma unroll
        for (int i = 0; i < 4; i++) {
            const int f4 = tid + 256 * i;
            const int r  = f4 >> 3;
            const int cc = (f4 & 7) * 4;
            int gr = row0 + r;
            if (gr > NN - 1) gr = NN - 1;
            const float4 v = *(const float4*)(x + (size_t)gr * DIN + k0 + cc);
            *(float4*)&xs[r][cc] = v;
        }
#pragma unroll
        for (int i = 0; i < 2; i++) {
            const int f4 = tid + 256 * i;
            const int r  = f4 >> 4;
            const int cc = (f4 & 15) * 4;
            const float4 v = *(const float4*)(wm + (size_t)(k0 + r) * DOUT + cc);
            *(float4*)&ws[r][cc] = v;
        }
        __syncthreads();

#pragma unroll
        for (int kk = 0; kk < 32; kk += 2) {
            const float4 w0 = *(const float4*)&ws[kk][c0];
            const float4 w1 = *(const float4*)&ws[kk + 1][c0];
#pragma unroll
            for (int i = 0; i < 8; i++) {
                const float2 xv = *(const float2*)&xs[r0 + i][kk];
                acc[i][0] += xv.x * w0.x;
                acc[i][1] += xv.x * w0.y;
                acc[i][2] += xv.x * w0.z;
                acc[i][3] += xv.x * w0.w;
                acc[i][0] += xv.y * w1.x;
                acc[i][1] += xv.y * w1.y;
                acc[i][2] += xv.y * w1.z;
                acc[i][3] += xv.y * w1.w;
            }
        }
        __syncthreads();
    }

#pragma unroll
    for (int i = 0; i < 8; i++) {
        const int gr = row0 + r0 + i;
        if (gr < NN) {
            float4 v;
            v.x = acc[i][0]; v.y = acc[i][1]; v.z = acc[i][2]; v.w = acc[i][3];
            *(float4*)&g_xp[(size_t)gr * DOUT + c0] = v;
        }
    }
}

// ---------------------------------------------------------------------------
// Kernel 2: weighted per-dim median.
// Keys: value with low-5 mantissa bits replaced by element index (distinct
// keys; <=31-ulp perturbation). Sort 17 keys with Green's 60-CE 16-sorter +
// 16-CE serial insertion of element 16 (76 CEs, 2 FMNMX each, bit-exact).
// Recover sorted weights via per-lane-replicated smem (conflict-free:
// bank == lane for every indexed read), then cumsum walk.
// ---------------------------------------------------------------------------
#define CE(A, B) do {                      \
    const float ka_ = k##A, kb_ = k##B;    \
    k##A = fminf(ka_, kb_);                \
    k##B = fmaxf(ka_, kb_);                \
} while (0)

__global__ void __launch_bounds__(256) median_kernel(
    const int*   __restrict__ col,
    const float* __restrict__ ew,
    const float* __restrict__ bias,
    float*       __restrict__ out)
{
    __shared__ float swt[4][KK];          // broadcast copy (total-weight sum)
    __shared__ int   soff[4][KK];
    __shared__ float wrep[4][KK][32];     // per-lane replicated weights

    const int tid   = threadIdx.x;
    const int local = tid >> 6;
    const int d     = tid & 63;
    const int lane  = tid & 31;
    const int node  = blockIdx.x * 4 + local;

    if (d < KK) {
        swt[local][d]  = ew[node * KK + d];
        soff[local][d] = col[node * KK + d] * DOUT;
    }
    // fill per-lane weight replicas: wrep[loc][j][ln] = ew[(blk*4+loc)*17+j]
    for (int i = tid; i < 4 * KK * 32; i += 256) {
        const int loc = i / (KK * 32);
        const int rem = i - loc * (KK * 32);
        const int j   = rem >> 5;
        const int ln  = rem & 31;
        wrep[loc][j][ln] = __ldg(&ew[(blockIdx.x * 4 + loc) * KK + j]);
    }
    __syncthreads();

    const float* __restrict__ xpd = g_xp + d;

    // load values, embed index into low 5 mantissa bits
#define LOADJ(J) float k##J = __uint_as_float(                                 \
        (__float_as_uint(__ldg(xpd + soff[local][J])) & 0xFFFFFFE0u) |         \
        (unsigned)J);
    LOADJ(0)  LOADJ(1)  LOADJ(2)  LOADJ(3)  LOADJ(4)  LOADJ(5)
    LOADJ(6)  LOADJ(7)  LOADJ(8)  LOADJ(9)  LOADJ(10) LOADJ(11)
    LOADJ(12) LOADJ(13) LOADJ(14) LOADJ(15) LOADJ(16)
#undef LOADJ

    const float* wl = swt[local];
    const float total =
        ((wl[0] + wl[1]) + (wl[2] + wl[3])) + ((wl[4] + wl[5]) + (wl[6] + wl[7])) +
        ((wl[8] + wl[9]) + (wl[10] + wl[11])) +
        ((wl[12] + wl[13]) + (wl[14] + wl[15])) + wl[16];
    const float hf = 0.5f * total;

    // --- Green's 16-element 60-CE sorting network on wires 0..15 ---
    CE(0,1);  CE(2,3);  CE(4,5);  CE(6,7);
    CE(8,9);  CE(10,11); CE(12,13); CE(14,15);

    CE(0,2);  CE(1,3);  CE(4,6);  CE(5,7);
    CE(8,10); CE(9,11); CE(12,14); CE(13,15);

    CE(0,4);  CE(1,5);  CE(2,6);  CE(3,7);
    CE(8,12); CE(9,13); CE(10,14); CE(11,15);

    CE(0,8);  CE(1,9);  CE(2,10); CE(3,11);
    CE(4,12); CE(5,13); CE(6,14); CE(7,15);

    CE(5,10); CE(6,9);  CE(3,12); CE(13,14);
    CE(7,11); CE(1,2);  CE(4,8);

    CE(1,4);  CE(7,13); CE(2,8);  CE(11,14);

    CE(2,4);  CE(5,6);  CE(9,10); CE(11,13);

    CE(3,8);  CE(7,12);

    CE(6,8);  CE(10,12); CE(3,5); CE(7,9);

    CE(3,4);  CE(5,6);  CE(7,8);  CE(9,10); CE(11,12);

    CE(6,7);  CE(8,9);

    // --- serial insertion of element 16 into the sorted 0..15 ---
    CE(15,16); CE(14,15); CE(13,14); CE(12,13);
    CE(11,12); CE(10,11); CE(9,10);  CE(8,9);
    CE(7,8);   CE(6,7);   CE(5,6);   CE(4,5);
    CE(3,4);   CE(2,3);   CE(1,2);   CE(0,1);

    // --- recover sorted weights: conflict-free (bank == lane always) ---
    const float* __restrict__ wr = &wrep[local][0][lane];
#define SWJ(J) const float sw##J = wr[(__float_as_uint(k##J) & 31u) * 32u];
    SWJ(0)  SWJ(1)  SWJ(2)  SWJ(3)  SWJ(4)  SWJ(5)  SWJ(6)  SWJ(7)  SWJ(8)
    SWJ(9)  SWJ(10) SWJ(11) SWJ(12) SWJ(13) SWJ(14) SWJ(15) SWJ(16)
#undef SWJ

    // --- cumsum walk: first sorted element with cumulative weight >= hf ---
    float cum = sw0;
    float med = k0;
#define STEP(J) med = (cum < hf) ? k##J : med; cum += sw##J;
    STEP(1)  STEP(2)  STEP(3)  STEP(4)  STEP(5)  STEP(6)  STEP(7)  STEP(8)
    STEP(9)  STEP(10) STEP(11) STEP(12) STEP(13) STEP(14) STEP(15) STEP(16)
#undef STEP

    const float medv = __uint_as_float(__float_as_uint(med) & 0xFFFFFFE0u);

    out[(size_t)node * DOUT + d] = total * medv + __ldg(&bias[d]);
}

// ---------------------------------------------------------------------------
// Inputs: x[N,128] f32, edge_index[2,E] i32, edge_weight[E] f32,
//         weight[128,64] f32, bias[64] f32. Output: [N,64] f32.
// ---------------------------------------------------------------------------
extern "C" void kernel_launch(void* const* d_in, const int* in_sizes, int n_in,
                              void* d_out, int out_size)
{
    const float* x    = (const float*)d_in[0];
    const int*   ei   = (const int*)  d_in[1];
    const float* ew   = (const float*)d_in[2];
    const float* wm   = (const float*)d_in[3];
    const float* bias = (const float*)d_in[4];
    float*       out  = (float*)d_out;

    const int E = in_sizes[1] / 2;
    const int* col = ei + E;

    gemm_kernel<<<(NN + 127) / 128, 256>>>(x, wm);
    median_kernel<<<NN / 4, 256>>>(col, ew, bias, out);
}

// round 8
// speedup vs baseline: 1.2620x; 1.2620x over previous
#include <cuda_runtime.h>
#include <cuda_bf16.h>

#define NN 50000
#define KK 17
#define DIN 128
#define DOUT 64

// Scratch for projected features xp = x @ W : [N, 64] fp32 = 12.8 MB (fits in L2)
__device__ float g_xp[(size_t)NN * DOUT];

// ---------------------------------------------------------------------------
// Kernel 1: xp = x @ W (fp32). R4 version — at the FFMA floor (~22us).
// ---------------------------------------------------------------------------
__global__ void __launch_bounds__(256) gemm_kernel(
    const float* __restrict__ x, const float* __restrict__ wm)
{
    __shared__ float xs[128][32];
    __shared__ float ws[32][64];

    const int tid  = threadIdx.x;
    const int row0 = blockIdx.x * 128;
    const int c0   = (tid & 15) * 4;
    const int r0   = (tid >> 4) * 8;

    float acc[8][4];
#pragma unroll
    for (int i = 0; i < 8; i++)
#pragma unroll
        for (int j = 0; j < 4; j++) acc[i][j] = 0.f;

    for (int k0 = 0; k0 < DIN; k0 += 32) {
#pragma unroll
        for (int i = 0; i < 4; i++) {
            const int f4 = tid + 256 * i;
            const int r  = f4 >> 3;
            const int cc = (f4 & 7) * 4;
            int gr = row0 + r;
            if (gr > NN - 1) gr = NN - 1;
            const float4 v = *(const float4*)(x + (size_t)gr * DIN + k0 + cc);
            *(float4*)&xs[r][cc] = v;
        }
#pragma unroll
        for (int i = 0; i < 2; i++) {
            const int f4 = tid + 256 * i;
            const int r  = f4 >> 4;
            const int cc = (f4 & 15) * 4;
            const float4 v = *(const float4*)(wm + (size_t)(k0 + r) * DOUT + cc);
            *(float4*)&ws[r][cc] = v;
        }
        __syncthreads();

#pragma unroll
        for (int kk = 0; kk < 32; kk += 2) {
            const float4 w0 = *(const float4*)&ws[kk][c0];
            const float4 w1 = *(const float4*)&ws[kk + 1][c0];
#pragma unroll
            for (int i = 0; i < 8; i++) {
                const float2 xv = *(const float2*)&xs[r0 + i][kk];
                acc[i][0] += xv.x * w0.x;
                acc[i][1] += xv.x * w0.y;
                acc[i][2] += xv.x * w0.z;
                acc[i][3] += xv.x * w0.w;
                acc[i][0] += xv.y * w1.x;
                acc[i][1] += xv.y * w1.y;
                acc[i][2] += xv.y * w1.z;
                acc[i][3] += xv.y * w1.w;
            }
        }
        __syncthreads();
    }

#pragma unroll
    for (int i = 0; i < 8; i++) {
        const int gr = row0 + r0 + i;
        if (gr < NN) {
            float4 v;
            v.x = acc[i][0]; v.y = acc[i][1]; v.z = acc[i][2]; v.w = acc[i][3];
            *(float4*)&g_xp[(size_t)gr * DOUT + c0] = v;
        }
    }
}

// ---------------------------------------------------------------------------
// Kernel 2: weighted per-dim median (R6 structure + 76-CE network from R7).
// Keys: value with low-5 mantissa bits replaced by element index (distinct
// keys; <=31-ulp perturbation). Sort via Green's 60-CE 16-sorter + 16-CE
// serial insertion of element 16 (2 FMNMX per CE, bit-exact so the index
// rides along). Recover sorted weights by direct indexed smem read, then
// cumsum walk.
// ---------------------------------------------------------------------------
#define CE(A, B) do {                      \
    const float ka_ = k##A, kb_ = k##B;    \
    k##A = fminf(ka_, kb_);                \
    k##B = fmaxf(ka_, kb_);                \
} while (0)

__global__ void __launch_bounds__(256) median_kernel(
    const int*   __restrict__ col,
    const float* __restrict__ ew,
    const float* __restrict__ bias,
    float*       __restrict__ out)
{
    __shared__ float swt[4][KK];
    __shared__ int   soff[4][KK];

    const int tid   = threadIdx.x;
    const int local = tid >> 6;
    const int d     = tid & 63;
    const int node  = blockIdx.x * 4 + local;

    if (d < KK) {
        swt[local][d]  = ew[node * KK + d];
        soff[local][d] = col[node * KK + d] * DOUT;
    }
    __syncthreads();

    const float* __restrict__ xpd = g_xp + d;

    // load values, embed index into low 5 mantissa bits (one LOP3 each)
#define LOADJ(J) float k##J = __uint_as_float(                                 \
        (__float_as_uint(__ldg(xpd + soff[local][J])) & 0xFFFFFFE0u) |         \
        (unsigned)J);
    LOADJ(0)  LOADJ(1)  LOADJ(2)  LOADJ(3)  LOADJ(4)  LOADJ(5)
    LOADJ(6)  LOADJ(7)  LOADJ(8)  LOADJ(9)  LOADJ(10) LOADJ(11)
    LOADJ(12) LOADJ(13) LOADJ(14) LOADJ(15) LOADJ(16)
#undef LOADJ

    const float* wl = swt[local];
    const float total =
        ((wl[0] + wl[1]) + (wl[2] + wl[3])) + ((wl[4] + wl[5]) + (wl[6] + wl[7])) +
        ((wl[8] + wl[9]) + (wl[10] + wl[11])) +
        ((wl[12] + wl[13]) + (wl[14] + wl[15])) + wl[16];
    const float hf = 0.5f * total;

    // --- Green's 16-element 60-CE sorting network on wires 0..15 ---
    CE(0,1);  CE(2,3);  CE(4,5);  CE(6,7);
    CE(8,9);  CE(10,11); CE(12,13); CE(14,15);

    CE(0,2);  CE(1,3);  CE(4,6);  CE(5,7);
    CE(8,10); CE(9,11); CE(12,14); CE(13,15);

    CE(0,4);  CE(1,5);  CE(2,6);  CE(3,7);
    CE(8,12); CE(9,13); CE(10,14); CE(11,15);

    CE(0,8);  CE(1,9);  CE(2,10); CE(3,11);
    CE(4,12); CE(5,13); CE(6,14); CE(7,15);

    CE(5,10); CE(6,9);  CE(3,12); CE(13,14);
    CE(7,11); CE(1,2);  CE(4,8);

    CE(1,4);  CE(7,13); CE(2,8);  CE(11,14);

    CE(2,4);  CE(5,6);  CE(9,10); CE(11,13);

    CE(3,8);  CE(7,12);

    CE(6,8);  CE(10,12); CE(3,5); CE(7,9);

    CE(3,4);  CE(5,6);  CE(7,8);  CE(9,10); CE(11,12);

    CE(6,7);  CE(8,9);

    // --- serial insertion of element 16 into the sorted 0..15 ---
    CE(15,16); CE(14,15); CE(13,14); CE(12,13);
    CE(11,12); CE(10,11); CE(9,10);  CE(8,9);
    CE(7,8);   CE(6,7);   CE(5,6);   CE(4,5);
    CE(3,4);   CE(2,3);   CE(1,2);   CE(0,1);

    // --- recover sorted weights by embedded index (direct indexed LDS) ---
#define SWJ(J) const float sw##J = wl[__float_as_uint(k##J) & 31u];
    SWJ(0)  SWJ(1)  SWJ(2)  SWJ(3)  SWJ(4)  SWJ(5)  SWJ(6)  SWJ(7)  SWJ(8)
    SWJ(9)  SWJ(10) SWJ(11) SWJ(12) SWJ(13) SWJ(14) SWJ(15) SWJ(16)
#undef SWJ

    // --- cumsum walk: first sorted element with cumulative weight >= hf ---
    float cum = sw0;
    float med = k0;
#define STEP(J) med = (cum < hf) ? k##J : med; cum += sw##J;
    STEP(1)  STEP(2)  STEP(3)  STEP(4)  STEP(5)  STEP(6)  STEP(7)  STEP(8)
    STEP(9)  STEP(10) STEP(11) STEP(12) STEP(13) STEP(14) STEP(15) STEP(16)
#undef STEP

    const float medv = __uint_as_float(__float_as_uint(med) & 0xFFFFFFE0u);

    out[(size_t)node * DOUT + d] = total * medv + __ldg(&bias[d]);
}

// ---------------------------------------------------------------------------
// Inputs: x[N,128] f32, edge_index[2,E] i32, edge_weight[E] f32,
//         weight[128,64] f32, bias[64] f32. Output: [N,64] f32.
// ---------------------------------------------------------------------------
extern "C" void kernel_launch(void* const* d_in, const int* in_sizes, int n_in,
                              void* d_out, int out_size)
{
    const float* x    = (const float*)d_in[0];
    const int*   ei   = (const int*)  d_in[1];
    const float* ew   = (const float*)d_in[2];
    const float* wm   = (const float*)d_in[3];
    const float* bias = (const float*)d_in[4];
    float*       out  = (float*)d_out;

    const int E = in_sizes[1] / 2;
    const int* col = ei + E;

    gemm_kernel<<<(NN + 127) / 128, 256>>>(x, wm);
    median_kernel<<<NN / 4, 256>>>(col, ew, bias, out);
}